// round 12
// baseline (speedup 1.0000x reference)
#include <cuda_runtime.h>

// Sparsemax attention, fp32.
// B=8, L=S=1024, H=16, E=D=64.
// out[b,l,h,d] = sum_s sparsemax_s( (1/8) * sum_e q[b,l,h,e]*k[b,s,h,e] ) * v[b,s,h,d]
//
// One CTA per (b, h, 32-row L tile). Scores for the whole row tile (32x1024 fp32)
// live in SMEM; tau per row found with Michelot's exact simplex-projection
// iteration (no sort needed).

#define NB 8
#define NL 1024
#define NS 1024
#define NH 16
#define NE 64
#define ND 64
#define MROWS 32     // L rows per CTA
#define TS   256     // S tile (== NT so K-load maps 1 thread : 1 s)
#define NT   256     // threads per CTA

// smem floats: Q tile + K^T/V tile (aliased) + scores + tau
#define SMEM_FLOATS (MROWS*NE + NE*TS + MROWS*NS + MROWS)
#define SMEM_BYTES  (SMEM_FLOATS * 4)

__device__ __forceinline__ float warp_sum_f(float v) {
#pragma unroll
    for (int o = 16; o > 0; o >>= 1) v += __shfl_xor_sync(0xffffffffu, v, o);
    return v;
}
__device__ __forceinline__ int warp_sum_i(int v) {
#pragma unroll
    for (int o = 16; o > 0; o >>= 1) v += __shfl_xor_sync(0xffffffffu, v, o);
    return v;
}

__global__ void __launch_bounds__(NT, 1)
sparsemax_attn_kernel(const float* __restrict__ Q, const float* __restrict__ K,
                      const float* __restrict__ V, float* __restrict__ O)
{
    extern __shared__ float sm[];
    float* sQ   = sm;                       // [MROWS][NE]        8 KB
    float* sKT  = sm + MROWS * NE;          // [NE][TS]          64 KB (aliased as sV[TS][ND])
    float* sS   = sKT + NE * TS;            // [MROWS][NS]      128 KB
    float* sTau = sS + MROWS * NS;          // [MROWS]

    const int ltile = blockIdx.x;           // 0..31
    const int h     = blockIdx.y;           // 0..15
    const int b     = blockIdx.z;           // 0..7
    const int l0    = ltile * MROWS;
    const int tid   = threadIdx.x;
    const int tx    = tid & 31;
    const int ty    = tid >> 5;             // warp id 0..7

    // ---------------- load Q tile [MROWS][NE] ----------------
    {
        for (int i = tid; i < MROWS * NE / 4; i += NT) {
            int row = i >> 4;               // / (NE/4)
            int eq  = i & 15;
            const float4 qv = reinterpret_cast<const float4*>(Q)
                [((size_t)((b * NL + l0 + row) * NH + h)) * (NE / 4) + eq];
            reinterpret_cast<float4*>(sQ)[row * (NE / 4) + eq] = qv;
        }
    }

    const float scale = 0.125f;             // 1/sqrt(64)

    // ---------------- QK^T: scores into sS ----------------
    for (int st = 0; st < NS / TS; ++st) {
        const int s0 = st * TS;
        // load K tile transposed into sKT[e][s]; thread t owns s_local = t
        {
            const float4* Kg = reinterpret_cast<const float4*>(
                K + ((size_t)((b * NS + s0 + tid) * NH + h)) * NE);
#pragma unroll
            for (int it = 0; it < NE / 4; ++it) {
                float4 kv = Kg[it];
                sKT[(it * 4 + 0) * TS + tid] = kv.x;
                sKT[(it * 4 + 1) * TS + tid] = kv.y;
                sKT[(it * 4 + 2) * TS + tid] = kv.z;
                sKT[(it * 4 + 3) * TS + tid] = kv.w;
            }
        }
        __syncthreads();

        // 4 rows x 8 cols micro-tile per thread
        float acc[4][8];
#pragma unroll
        for (int i = 0; i < 4; i++)
#pragma unroll
            for (int j = 0; j < 8; j++) acc[i][j] = 0.f;

#pragma unroll 8
        for (int e = 0; e < NE; ++e) {
            float av[4];
#pragma unroll
            for (int i = 0; i < 4; i++) av[i] = sQ[(ty + 8 * i) * NE + e];   // broadcast
            float bv[8];
#pragma unroll
            for (int j = 0; j < 8; j++) bv[j] = sKT[e * TS + tx + 32 * j];   // conflict-free
#pragma unroll
            for (int i = 0; i < 4; i++)
#pragma unroll
                for (int j = 0; j < 8; j++)
                    acc[i][j] = fmaf(av[i], bv[j], acc[i][j]);
        }

#pragma unroll
        for (int i = 0; i < 4; i++)
#pragma unroll
            for (int j = 0; j < 8; j++)
                sS[(ty + 8 * i) * NS + s0 + tx + 32 * j] = acc[i][j] * scale;
        __syncthreads();
    }

    // ---------------- sparsemax tau per row (Michelot) ----------------
    // warp ty handles rows 4*ty .. 4*ty+3; row cached in 32 regs per lane
    {
#pragma unroll
        for (int rr = 0; rr < 4; ++rr) {
            const int r = ty * 4 + rr;
            const float* row = sS + r * NS;
            float z[32];
#pragma unroll
            for (int k = 0; k < 32; k++) z[k] = row[tx + 32 * k];

            float s = 0.f;
#pragma unroll
            for (int k = 0; k < 32; k++) s += z[k];
            s = warp_sum_f(s);
            float tau = (s - 1.0f) * (1.0f / (float)NS);
            int prev = NS;
            for (int iter = 0; iter < 64; ++iter) {
                float ss = 0.f; int c = 0;
#pragma unroll
                for (int k = 0; k < 32; k++) {
                    float v = z[k];
                    if (v > tau) { ss += v; c += 1; }
                }
                ss = warp_sum_f(ss);
                c  = warp_sum_i(c);
                tau = (ss - 1.0f) / (float)c;   // c >= 1 always (max elem stays active)
                if (c == prev) break;            // active set stable -> converged (exact)
                prev = c;
            }
            if (tx == 0) sTau[r] = tau;
        }
    }
    __syncthreads();

    // ---------------- scores -> A in place: a = max(z - tau, 0) ----------------
    {
        float4* sS4 = reinterpret_cast<float4*>(sS);
        for (int i = tid; i < MROWS * NS / 4; i += NT) {
            int r = i >> 8;                 // / (NS/4)
            float tau = sTau[r];
            float4 v = sS4[i];
            v.x = fmaxf(v.x - tau, 0.f);
            v.y = fmaxf(v.y - tau, 0.f);
            v.z = fmaxf(v.z - tau, 0.f);
            v.w = fmaxf(v.w - tau, 0.f);
            sS4[i] = v;
        }
    }
    __syncthreads();

    // ---------------- A @ V ----------------
    float oa[4][2];
#pragma unroll
    for (int i = 0; i < 4; i++) { oa[i][0] = 0.f; oa[i][1] = 0.f; }

    float* sV = sKT;                        // alias: [TS][ND]
    for (int st = 0; st < NS / TS; ++st) {
        const int s0 = st * TS;
        __syncthreads();                    // guard sV overwrite vs prior reads
        {
            for (int i = tid; i < TS * (ND / 4); i += NT) {
                int sl = i >> 4;            // / (ND/4)
                int dq = i & 15;
                const float4 vv = reinterpret_cast<const float4*>(
                    V + ((size_t)((b * NS + s0 + sl) * NH + h)) * ND)[dq];
                reinterpret_cast<float4*>(sV + sl * ND)[dq] = vv;
            }
        }
        __syncthreads();

#pragma unroll 4
        for (int s = 0; s < TS; ++s) {
            float a0 = sS[(ty +  0) * NS + s0 + s];   // broadcast reads
            float a1 = sS[(ty +  8) * NS + s0 + s];
            float a2 = sS[(ty + 16) * NS + s0 + s];
            float a3 = sS[(ty + 24) * NS + s0 + s];
            float v0 = sV[s * ND + tx];               // conflict-free
            float v1 = sV[s * ND + tx + 32];
            oa[0][0] = fmaf(a0, v0, oa[0][0]);  oa[0][1] = fmaf(a0, v1, oa[0][1]);
            oa[1][0] = fmaf(a1, v0, oa[1][0]);  oa[1][1] = fmaf(a1, v1, oa[1][1]);
            oa[2][0] = fmaf(a2, v0, oa[2][0]);  oa[2][1] = fmaf(a2, v1, oa[2][1]);
            oa[3][0] = fmaf(a3, v0, oa[3][0]);  oa[3][1] = fmaf(a3, v1, oa[3][1]);
        }
    }

    // ---------------- write out [b, l, h, d] ----------------
#pragma unroll
    for (int i = 0; i < 4; i++) {
        int l = l0 + ty + 8 * i;
        float* o = O + ((size_t)((b * NL + l) * NH + h)) * ND;
        o[tx]      = oa[i][0];
        o[tx + 32] = oa[i][1];
    }
}

extern "C" void kernel_launch(void* const* d_in, const int* in_sizes, int n_in,
                              void* d_out, int out_size) {
    const float* Q = (const float*)d_in[0];   // queries [B,L,H,E]
    const float* K = (const float*)d_in[1];   // keys    [B,S,H,E]
    const float* V = (const float*)d_in[2];   // values  [B,S,H,D]
    float* O = (float*)d_out;                 // out     [B,L,H,D]

    cudaFuncSetAttribute(sparsemax_attn_kernel,
                         cudaFuncAttributeMaxDynamicSharedMemorySize, SMEM_BYTES);
    dim3 grid(NL / MROWS, NH, NB);
    sparsemax_attn_kernel<<<grid, NT, SMEM_BYTES>>>(Q, K, V, O);
}